// round 4
// baseline (speedup 1.0000x reference)
#include <cuda_runtime.h>
#include <mma.h>
#include <math.h>

using namespace nvcuda;

#define N_NODES 50000
#define NPAD 50048            // 391 * 128, padded rows for wmma epilogue
#define FIN 128
#define H1 8
#define F1 128
#define E_MAX 800000
#define ET_MAX (E_MAX + N_NODES)
#define NEG_SLOPE 0.2f
#define NEG_INF __int_as_float(0xff800000)
#define SCAN_NB ((N_NODES + 1023) / 1024)   // 49

// ------------------------- scratch -------------------------
__device__ float g_h1[NPAD * F1];
__device__ float g_agg1[N_NODES * F1];
__device__ float g_asrc[N_NODES * H1];
__device__ float g_adst[N_NODES * H1];
__device__ float g_h2[N_NODES * 2];
__device__ float g_a2s[N_NODES];
__device__ float g_a2d[N_NODES];
__device__ int   g_src[ET_MAX];
__device__ int   g_dst[ET_MAX];
__device__ int   g_csr_src[ET_MAX];
__device__ int   g_start[N_NODES + 1];
__device__ int   g_deg[N_NODES];
__device__ int   g_cnt[N_NODES];
__device__ int   g_bsum[SCAN_NB];
__device__ int   g_boff[SCAN_NB];
__device__ int   g_is64;

__device__ __forceinline__ float leaky(float v) { return v > 0.f ? v : NEG_SLOPE * v; }

// ------------------------- dtype probe -------------------------
__global__ void probe_kernel(const void* ei) {
    const long long* p = (const long long*)ei;
    int bad = 0;
    for (int i = threadIdx.x; i < 2048; i += 256) {
        long long v = p[i];
        if (v < 0 || v >= (long long)N_NODES) bad = 1;
    }
    bad = __syncthreads_or(bad);
    if (threadIdx.x == 0) g_is64 = bad ? 0 : 1;
}

__global__ void zero_kernel() {
    int i = blockIdx.x * blockDim.x + threadIdx.x;
    if (i < N_NODES) { g_deg[i] = 0; g_cnt[i] = 0; }
}

__global__ void convert_kernel(const void* ei, int E, int ET) {
    int i = blockIdx.x * blockDim.x + threadIdx.x;
    if (i >= ET) return;
    int s, d;
    if (i < E) {
        if (g_is64) {
            const long long* p = (const long long*)ei;
            s = (int)p[i]; d = (int)p[E + i];
        } else {
            const int* p = (const int*)ei;
            s = p[i]; d = p[E + i];
        }
    } else {
        s = d = i - E;
    }
    g_src[i] = s;
    g_dst[i] = d;
    atomicAdd(&g_deg[d], 1);
}

// ------------------------- multi-block scan -------------------------
__global__ void scanA_kernel() {
    int i = blockIdx.x * 1024 + threadIdx.x;
    int v = (i < N_NODES) ? g_deg[i] : 0;
    int lane = threadIdx.x & 31, wid = threadIdx.x >> 5;
    int x = v;
#pragma unroll
    for (int o = 1; o < 32; o <<= 1) {
        int t = __shfl_up_sync(0xffffffffu, x, o);
        if (lane >= o) x += t;
    }
    __shared__ int wsum[32];
    if (lane == 31) wsum[wid] = x;
    __syncthreads();
    if (wid == 0) {
        int y = wsum[lane];
#pragma unroll
        for (int o = 1; o < 32; o <<= 1) {
            int t = __shfl_up_sync(0xffffffffu, y, o);
            if (lane >= o) y += t;
        }
        wsum[lane] = y;
    }
    __syncthreads();
    int incl = x + (wid > 0 ? wsum[wid - 1] : 0);
    if (i < N_NODES) g_start[i] = incl - v;
    if (threadIdx.x == 1023) g_bsum[blockIdx.x] = incl;
}

__global__ void scanB_kernel() {
    int lane = threadIdx.x;
    int i0 = 2 * lane, i1 = 2 * lane + 1;
    int a = (i0 < SCAN_NB) ? g_bsum[i0] : 0;
    int b = (i1 < SCAN_NB) ? g_bsum[i1] : 0;
    int loc = a + b;
    int x = loc;
#pragma unroll
    for (int o = 1; o < 32; o <<= 1) {
        int t = __shfl_up_sync(0xffffffffu, x, o);
        if (lane >= o) x += t;
    }
    int excl = x - loc;
    if (i0 < SCAN_NB) g_boff[i0] = excl;
    if (i1 < SCAN_NB) g_boff[i1] = excl + a;
    if (lane == 31) g_start[N_NODES] = x;
}

__global__ void scanC_kernel() {
    int i = blockIdx.x * blockDim.x + threadIdx.x;
    if (i < N_NODES) g_start[i] += g_boff[i >> 10];
}

__global__ void scatter_kernel(int ET) {
    int i = blockIdx.x * blockDim.x + threadIdx.x;
    if (i >= ET) return;
    int d = g_dst[i];
    int pos = g_start[d] + atomicAdd(&g_cnt[d], 1);
    g_csr_src[pos] = g_src[i];
}

// ------------------------- TF32 tensor-core GEMM: h1 = x @ W1 (3xTF32 split) -------------------------
#define BM 128
#define BKT 16
#define LDA 136   // padded lds (multiple of 8)
__global__ void __launch_bounds__(512)
gemm1_tc_kernel(const float* __restrict__ X, const float* __restrict__ W, int M) {
    __shared__ __align__(16) float Ahi[BKT][LDA];
    __shared__ __align__(16) float Alo[BKT][LDA];
    __shared__ __align__(16) float Bhi[BKT][LDA];
    __shared__ __align__(16) float Blo[BKT][LDA];

    int tid = threadIdx.x;
    int wid = tid >> 5;
    int wm = wid >> 2;        // 0..3
    int wn = wid & 3;         // 0..3
    int rowBase = blockIdx.x * BM;

    // loader indices
    int arow = tid >> 2;               // 0..127
    int aquad = (tid & 3) * 4;         // 0,4,8,12
    int grow = rowBase + arow;
    const float* Xrow = X + (size_t)grow * FIN;
    int brow = tid >> 5;               // 0..15
    int bcol = (tid & 31) * 4;         // 0..124

    wmma::fragment<wmma::accumulator, 16, 16, 8, float> acc[2][2];
#pragma unroll
    for (int i = 0; i < 2; i++)
#pragma unroll
        for (int j = 0; j < 2; j++) wmma::fill_fragment(acc[i][j], 0.f);

    for (int k0 = 0; k0 < FIN; k0 += BKT) {
        // load X tile (128 x 16) transposed into Ahi/Alo[k][m]
        float4 xv = make_float4(0.f, 0.f, 0.f, 0.f);
        if (grow < M) xv = *(const float4*)(Xrow + k0 + aquad);
        {
            float v[4] = {xv.x, xv.y, xv.z, xv.w};
#pragma unroll
            for (int c = 0; c < 4; c++) {
                float hi = wmma::__float_to_tf32(v[c]);
                Ahi[aquad + c][arow] = hi;
                Alo[aquad + c][arow] = v[c] - hi;
            }
        }
        // load W tile (16 x 128)
        {
            float4 wv = *(const float4*)&W[(size_t)(k0 + brow) * F1 + bcol];
            float v[4] = {wv.x, wv.y, wv.z, wv.w};
            float hi4[4], lo4[4];
#pragma unroll
            for (int c = 0; c < 4; c++) {
                hi4[c] = wmma::__float_to_tf32(v[c]);
                lo4[c] = v[c] - hi4[c];
            }
            *(float4*)&Bhi[brow][bcol] = make_float4(hi4[0], hi4[1], hi4[2], hi4[3]);
            *(float4*)&Blo[brow][bcol] = make_float4(lo4[0], lo4[1], lo4[2], lo4[3]);
        }
        __syncthreads();

#pragma unroll
        for (int kk = 0; kk < BKT; kk += 8) {
            wmma::fragment<wmma::matrix_a, 16, 16, 8, wmma::precision::tf32, wmma::col_major> ah[2], al[2];
            wmma::fragment<wmma::matrix_b, 16, 16, 8, wmma::precision::tf32, wmma::row_major> bh[2], bl[2];
#pragma unroll
            for (int i = 0; i < 2; i++) {
                wmma::load_matrix_sync(ah[i], &Ahi[kk][wm * 32 + i * 16], LDA);
                wmma::load_matrix_sync(al[i], &Alo[kk][wm * 32 + i * 16], LDA);
#pragma unroll
                for (int t = 0; t < ah[i].num_elements; t++) {
                    ah[i].x[t] = wmma::__float_to_tf32(ah[i].x[t]);
                    al[i].x[t] = wmma::__float_to_tf32(al[i].x[t]);
                }
            }
#pragma unroll
            for (int j = 0; j < 2; j++) {
                wmma::load_matrix_sync(bh[j], &Bhi[kk][wn * 32 + j * 16], LDA);
                wmma::load_matrix_sync(bl[j], &Blo[kk][wn * 32 + j * 16], LDA);
#pragma unroll
                for (int t = 0; t < bh[j].num_elements; t++) {
                    bh[j].x[t] = wmma::__float_to_tf32(bh[j].x[t]);
                    bl[j].x[t] = wmma::__float_to_tf32(bl[j].x[t]);
                }
            }
#pragma unroll
            for (int i = 0; i < 2; i++)
#pragma unroll
                for (int j = 0; j < 2; j++) {
                    wmma::mma_sync(acc[i][j], ah[i], bh[j], acc[i][j]);
                    wmma::mma_sync(acc[i][j], ah[i], bl[j], acc[i][j]);
                    wmma::mma_sync(acc[i][j], al[i], bh[j], acc[i][j]);
                }
        }
        __syncthreads();
    }

    // epilogue: direct fragment store to (padded) g_h1
#pragma unroll
    for (int i = 0; i < 2; i++)
#pragma unroll
        for (int j = 0; j < 2; j++) {
            int gr = rowBase + wm * 32 + i * 16;
            int gc = wn * 32 + j * 16;
            wmma::store_matrix_sync(&g_h1[(size_t)gr * F1 + gc], acc[i][j], F1, wmma::mem_row_major);
        }
}

// ------------------------- attention dots (warp per node) -------------------------
__global__ void attdot_kernel(const float* __restrict__ att_s, const float* __restrict__ att_d) {
    int n = (blockIdx.x * blockDim.x + threadIdx.x) >> 5;
    if (n >= N_NODES) return;
    int lane = threadIdx.x & 31;
    float4 hv = *(const float4*)&g_h1[(size_t)n * F1 + lane * 4];
    float4 as = *(const float4*)&att_s[lane * 4];
    float4 ad = *(const float4*)&att_d[lane * 4];
    float ps = hv.x * as.x + hv.y * as.y + hv.z * as.z + hv.w * as.w;
    float pd = hv.x * ad.x + hv.y * ad.y + hv.z * ad.z + hv.w * ad.w;
    ps += __shfl_xor_sync(0xffffffffu, ps, 1);
    ps += __shfl_xor_sync(0xffffffffu, ps, 2);
    pd += __shfl_xor_sync(0xffffffffu, pd, 1);
    pd += __shfl_xor_sync(0xffffffffu, pd, 2);
    if ((lane & 3) == 0) {
        int h = lane >> 2;
        g_asrc[n * H1 + h] = ps;
        g_adst[n * H1 + h] = pd;
    }
}

// ------------------------- fused layer-1 softmax + aggregation -------------------------
__global__ void node1_kernel() {
    int n = (blockIdx.x * blockDim.x + threadIdx.x) >> 5;
    if (n >= N_NODES) return;
    int lane = threadIdx.x & 31;
    int rs = g_start[n], re = g_start[n + 1];

    float4 ad0 = *(const float4*)&g_adst[n * H1];
    float4 ad1 = *(const float4*)&g_adst[n * H1 + 4];
    float adh[8] = {ad0.x, ad0.y, ad0.z, ad0.w, ad1.x, ad1.y, ad1.z, ad1.w};

    float m[8];
#pragma unroll
    for (int h = 0; h < 8; h++) m[h] = NEG_INF;
    for (int j = rs + lane; j < re; j += 32) {
        int s = g_csr_src[j];
        float4 a0 = *(const float4*)&g_asrc[s * H1];
        float4 a1 = *(const float4*)&g_asrc[s * H1 + 4];
        float ev[8] = {a0.x + adh[0], a0.y + adh[1], a0.z + adh[2], a0.w + adh[3],
                       a1.x + adh[4], a1.y + adh[5], a1.z + adh[6], a1.w + adh[7]};
#pragma unroll
        for (int h = 0; h < 8; h++) m[h] = fmaxf(m[h], leaky(ev[h]));
    }
#pragma unroll
    for (int o = 16; o > 0; o >>= 1)
#pragma unroll
        for (int h = 0; h < 8; h++) m[h] = fmaxf(m[h], __shfl_xor_sync(0xffffffffu, m[h], o));

    int myh = lane >> 2;
    float mh = m[myh];
    float adm = adh[myh];
    float ssum = 0.f;
    float acc0 = 0.f, acc1 = 0.f, acc2 = 0.f, acc3 = 0.f;

    int j = rs;
    for (; j + 3 < re; j += 4) {
        int s0 = g_csr_src[j];
        int s1 = g_csr_src[j + 1];
        int s2 = g_csr_src[j + 2];
        int s3 = g_csr_src[j + 3];
        float av0 = __ldg(&g_asrc[s0 * H1 + myh]);
        float av1 = __ldg(&g_asrc[s1 * H1 + myh]);
        float av2 = __ldg(&g_asrc[s2 * H1 + myh]);
        float av3 = __ldg(&g_asrc[s3 * H1 + myh]);
        float4 hv0 = *(const float4*)&g_h1[(size_t)s0 * F1 + lane * 4];
        float4 hv1 = *(const float4*)&g_h1[(size_t)s1 * F1 + lane * 4];
        float4 hv2 = *(const float4*)&g_h1[(size_t)s2 * F1 + lane * 4];
        float4 hv3 = *(const float4*)&g_h1[(size_t)s3 * F1 + lane * 4];
        float ee0 = __expf(leaky(av0 + adm) - mh);
        float ee1 = __expf(leaky(av1 + adm) - mh);
        float ee2 = __expf(leaky(av2 + adm) - mh);
        float ee3 = __expf(leaky(av3 + adm) - mh);
        ssum += (ee0 + ee1) + (ee2 + ee3);
        acc0 += ee0 * hv0.x + ee1 * hv1.x + ee2 * hv2.x + ee3 * hv3.x;
        acc1 += ee0 * hv0.y + ee1 * hv1.y + ee2 * hv2.y + ee3 * hv3.y;
        acc2 += ee0 * hv0.z + ee1 * hv1.z + ee2 * hv2.z + ee3 * hv3.z;
        acc3 += ee0 * hv0.w + ee1 * hv1.w + ee2 * hv2.w + ee3 * hv3.w;
    }
    for (; j < re; j++) {
        int s0 = g_csr_src[j];
        float av0 = __ldg(&g_asrc[s0 * H1 + myh]);
        float4 hv0 = *(const float4*)&g_h1[(size_t)s0 * F1 + lane * 4];
        float ee0 = __expf(leaky(av0 + adm) - mh);
        ssum += ee0;
        acc0 += ee0 * hv0.x; acc1 += ee0 * hv0.y; acc2 += ee0 * hv0.z; acc3 += ee0 * hv0.w;
    }
    float inv = 1.f / ssum;
    *(float4*)&g_agg1[(size_t)n * F1 + lane * 4] =
        make_float4(acc0 * inv, acc1 * inv, acc2 * inv, acc3 * inv);
}

// ------------------------- layer 2 projection -------------------------
__global__ void h2_kernel(const float* __restrict__ b1, const float* __restrict__ W2,
                          const float* __restrict__ as2, const float* __restrict__ ad2) {
    int n = (blockIdx.x * blockDim.x + threadIdx.x) >> 5;
    if (n >= N_NODES) return;
    int lane = threadIdx.x & 31;
    float4 hv = *(const float4*)&g_agg1[(size_t)n * F1 + lane * 4];
    float4 bv = *(const float4*)&b1[lane * 4];
    float v0 = hv.x + bv.x, v1 = hv.y + bv.y, v2 = hv.z + bv.z, v3 = hv.w + bv.w;
    v0 = v0 > 0.f ? v0 : expm1f(v0);
    v1 = v1 > 0.f ? v1 : expm1f(v1);
    v2 = v2 > 0.f ? v2 : expm1f(v2);
    v3 = v3 > 0.f ? v3 : expm1f(v3);
    const float4* W4 = (const float4*)W2;
    float4 wa = W4[lane * 2];
    float4 wb = W4[lane * 2 + 1];
    float p0 = v0 * wa.x + v1 * wa.z + v2 * wb.x + v3 * wb.z;
    float p1 = v0 * wa.y + v1 * wa.w + v2 * wb.y + v3 * wb.w;
#pragma unroll
    for (int o = 16; o > 0; o >>= 1) {
        p0 += __shfl_xor_sync(0xffffffffu, p0, o);
        p1 += __shfl_xor_sync(0xffffffffu, p1, o);
    }
    if (lane == 0) {
        g_h2[n * 2] = p0;
        g_h2[n * 2 + 1] = p1;
        g_a2s[n] = p0 * as2[0] + p1 * as2[1];
        g_a2d[n] = p0 * ad2[0] + p1 * ad2[1];
    }
}

// ------------------------- fused layer-2 softmax-aggregate -------------------------
__global__ void node2_kernel(float* __restrict__ out, const float* __restrict__ b2) {
    int n = (blockIdx.x * blockDim.x + threadIdx.x) >> 5;
    if (n >= N_NODES) return;
    int lane = threadIdx.x & 31;
    int rs = g_start[n], re = g_start[n + 1];
    float a2dn = g_a2d[n];

    float m = NEG_INF;
    for (int j = rs + lane; j < re; j += 32)
        m = fmaxf(m, leaky(g_a2s[g_csr_src[j]] + a2dn));
#pragma unroll
    for (int o = 16; o > 0; o >>= 1) m = fmaxf(m, __shfl_xor_sync(0xffffffffu, m, o));

    float S = 0.f, n0 = 0.f, n1 = 0.f;
    for (int j = rs + lane; j < re; j += 32) {
        int s = g_csr_src[j];
        float ee = __expf(leaky(g_a2s[s] + a2dn) - m);
        float2 h = *(const float2*)&g_h2[s * 2];
        S += ee; n0 += ee * h.x; n1 += ee * h.y;
    }
#pragma unroll
    for (int o = 16; o > 0; o >>= 1) {
        S  += __shfl_xor_sync(0xffffffffu, S, o);
        n0 += __shfl_xor_sync(0xffffffffu, n0, o);
        n1 += __shfl_xor_sync(0xffffffffu, n1, o);
    }
    if (lane == 0) {
        float inv = 1.f / S;
        out[n * 2]     = n0 * inv + b2[0];
        out[n * 2 + 1] = n1 * inv + b2[1];
    }
}

// ------------------------- launch -------------------------
extern "C" void kernel_launch(void* const* d_in, const int* in_sizes, int n_in,
                              void* d_out, int out_size) {
    const float* x   = (const float*)d_in[0];
    const void*  ei  = d_in[1];
    const float* W1  = (const float*)d_in[2];
    const float* as1 = (const float*)d_in[3];
    const float* ad1 = (const float*)d_in[4];
    const float* b1  = (const float*)d_in[5];
    const float* W2  = (const float*)d_in[6];
    const float* as2 = (const float*)d_in[7];
    const float* ad2 = (const float*)d_in[8];
    const float* b2  = (const float*)d_in[9];
    float* out = (float*)d_out;

    int E  = in_sizes[1] / 2;
    int ET = E + N_NODES;

    probe_kernel<<<1, 256>>>(ei);
    zero_kernel<<<(N_NODES + 255) / 256, 256>>>();
    convert_kernel<<<(ET + 255) / 256, 256>>>(ei, E, ET);
    scanA_kernel<<<SCAN_NB, 1024>>>();
    scanB_kernel<<<1, 32>>>();
    scanC_kernel<<<(N_NODES + 255) / 256, 256>>>();
    scatter_kernel<<<(ET + 255) / 256, 256>>>(ET);

    gemm1_tc_kernel<<<(N_NODES + BM - 1) / BM, 512>>>(x, W1, N_NODES);

    int nodeBlocks = (N_NODES * 32 + 255) / 256;
    attdot_kernel<<<nodeBlocks, 256>>>(as1, ad1);
    node1_kernel<<<nodeBlocks, 256>>>();
    h2_kernel<<<nodeBlocks, 256>>>(b1, W2, as2, ad2);
    node2_kernel<<<nodeBlocks, 256>>>(out, b2);
}

// round 5
// speedup vs baseline: 1.1187x; 1.1187x over previous
#include <cuda_runtime.h>
#include <cuda_fp16.h>
#include <math.h>

#define N_NODES 50000
#define FIN 128
#define H1 8
#define F1 128
#define E_MAX 800000
#define ET_MAX (E_MAX + N_NODES)
#define NEG_SLOPE 0.2f
#define NEG_INF __int_as_float(0xff800000)
#define SCAN_NB ((N_NODES + 1023) / 1024)   // 49

// ------------------------- scratch -------------------------
__device__ __half g_h1h[N_NODES * F1];     // fp16 copy of x @ W1 (node1 gathers)
__device__ float g_agg1[N_NODES * F1];
__device__ float g_asrc[N_NODES * H1];
__device__ float g_adst[N_NODES * H1];
__device__ float g_h2[N_NODES * 2];
__device__ float g_a2s[N_NODES];
__device__ float g_a2d[N_NODES];
__device__ int   g_src[ET_MAX];
__device__ int   g_dst[ET_MAX];
__device__ int   g_csr_src[ET_MAX];
__device__ int   g_start[N_NODES + 1];
__device__ int   g_deg[N_NODES];
__device__ int   g_cnt[N_NODES];
__device__ int   g_bsum[SCAN_NB];
__device__ int   g_boff[SCAN_NB];
__device__ int   g_is64;

__device__ __forceinline__ float leaky(float v) { return v > 0.f ? v : NEG_SLOPE * v; }

// ------------------------- dtype probe -------------------------
__global__ void probe_kernel(const void* ei) {
    const long long* p = (const long long*)ei;
    int bad = 0;
    for (int i = threadIdx.x; i < 2048; i += 256) {
        long long v = p[i];
        if (v < 0 || v >= (long long)N_NODES) bad = 1;
    }
    bad = __syncthreads_or(bad);
    if (threadIdx.x == 0) g_is64 = bad ? 0 : 1;
}

__global__ void zero_kernel() {
    int i = blockIdx.x * blockDim.x + threadIdx.x;
    if (i < N_NODES) { g_deg[i] = 0; g_cnt[i] = 0; }
}

__global__ void convert_kernel(const void* ei, int E, int ET) {
    int i = blockIdx.x * blockDim.x + threadIdx.x;
    if (i >= ET) return;
    int s, d;
    if (i < E) {
        if (g_is64) {
            const long long* p = (const long long*)ei;
            s = (int)p[i]; d = (int)p[E + i];
        } else {
            const int* p = (const int*)ei;
            s = p[i]; d = p[E + i];
        }
    } else {
        s = d = i - E;
    }
    g_src[i] = s;
    g_dst[i] = d;
    atomicAdd(&g_deg[d], 1);
}

// ------------------------- multi-block scan -------------------------
__global__ void scanA_kernel() {
    int i = blockIdx.x * 1024 + threadIdx.x;
    int v = (i < N_NODES) ? g_deg[i] : 0;
    int lane = threadIdx.x & 31, wid = threadIdx.x >> 5;
    int x = v;
#pragma unroll
    for (int o = 1; o < 32; o <<= 1) {
        int t = __shfl_up_sync(0xffffffffu, x, o);
        if (lane >= o) x += t;
    }
    __shared__ int wsum[32];
    if (lane == 31) wsum[wid] = x;
    __syncthreads();
    if (wid == 0) {
        int y = wsum[lane];
#pragma unroll
        for (int o = 1; o < 32; o <<= 1) {
            int t = __shfl_up_sync(0xffffffffu, y, o);
            if (lane >= o) y += t;
        }
        wsum[lane] = y;
    }
    __syncthreads();
    int incl = x + (wid > 0 ? wsum[wid - 1] : 0);
    if (i < N_NODES) g_start[i] = incl - v;
    if (threadIdx.x == 1023) g_bsum[blockIdx.x] = incl;
}

__global__ void scanB_kernel() {
    int lane = threadIdx.x;
    int i0 = 2 * lane, i1 = 2 * lane + 1;
    int a = (i0 < SCAN_NB) ? g_bsum[i0] : 0;
    int b = (i1 < SCAN_NB) ? g_bsum[i1] : 0;
    int loc = a + b;
    int x = loc;
#pragma unroll
    for (int o = 1; o < 32; o <<= 1) {
        int t = __shfl_up_sync(0xffffffffu, x, o);
        if (lane >= o) x += t;
    }
    int excl = x - loc;
    if (i0 < SCAN_NB) g_boff[i0] = excl;
    if (i1 < SCAN_NB) g_boff[i1] = excl + a;
    if (lane == 31) g_start[N_NODES] = x;
}

__global__ void scanC_kernel() {
    int i = blockIdx.x * blockDim.x + threadIdx.x;
    if (i < N_NODES) g_start[i] += g_boff[i >> 10];
}

__global__ void scatter_kernel(int ET) {
    int i = blockIdx.x * blockDim.x + threadIdx.x;
    if (i >= ET) return;
    int d = g_dst[i];
    int pos = g_start[d] + atomicAdd(&g_cnt[d], 1);
    g_csr_src[pos] = g_src[i];
}

// ------------------------- GEMM: h1 = x @ W1 (M x 128 x 128), 128x128 tile, 8x8 micro -------------------------
#define BM 128
#define BK 8
__global__ void __launch_bounds__(256, 2)
gemm1_kernel(const float* __restrict__ X, const float* __restrict__ W,
             const float* __restrict__ att_s, const float* __restrict__ att_d, int M) {
    __shared__ __align__(16) float As[BK][BM];
    __shared__ __align__(16) float Bs[BK][F1];
    __shared__ float s_as[F1], s_ad[F1];
    int tid = threadIdx.x;
    int tx = tid & 15;
    int ty = tid >> 4;
    int rowBase = blockIdx.x * BM;

    if (tid < F1) { s_as[tid] = att_s[tid]; s_ad[tid] = att_d[tid]; }

    int lrow = tid >> 1;
    int lhalf = tid & 1;
    int grow = rowBase + lrow;
    const float* Xrow = X + (size_t)grow * FIN;
    int wrow = tid >> 5;
    int wcol = (tid & 31) * 4;

    float acc[8][8];
#pragma unroll
    for (int i = 0; i < 8; i++)
#pragma unroll
        for (int j = 0; j < 8; j++) acc[i][j] = 0.f;

    for (int k0 = 0; k0 < FIN; k0 += BK) {
        float4 xv = make_float4(0.f, 0.f, 0.f, 0.f);
        if (grow < M) xv = *(const float4*)(Xrow + k0 + lhalf * 4);
        As[lhalf * 4 + 0][lrow] = xv.x;
        As[lhalf * 4 + 1][lrow] = xv.y;
        As[lhalf * 4 + 2][lrow] = xv.z;
        As[lhalf * 4 + 3][lrow] = xv.w;
        *(float4*)&Bs[wrow][wcol] = *(const float4*)&W[(size_t)(k0 + wrow) * F1 + wcol];
        __syncthreads();
#pragma unroll
        for (int kk = 0; kk < BK; kk++) {
            float4 a0 = *(const float4*)&As[kk][ty * 8];
            float4 a1 = *(const float4*)&As[kk][ty * 8 + 4];
            float4 b0 = *(const float4*)&Bs[kk][tx * 8];
            float4 b1 = *(const float4*)&Bs[kk][tx * 8 + 4];
            float av[8] = {a0.x, a0.y, a0.z, a0.w, a1.x, a1.y, a1.z, a1.w};
            float bv[8] = {b0.x, b0.y, b0.z, b0.w, b1.x, b1.y, b1.z, b1.w};
#pragma unroll
            for (int i = 0; i < 8; i++)
#pragma unroll
                for (int j = 0; j < 8; j++) acc[i][j] += av[i] * bv[j];
        }
        __syncthreads();
    }

    // epilogue: fp16 h1 store + fused attention dots (fp32 accumulators)
    int head = tx >> 1;
    int cbase = head * 16 + (tx & 1) * 8;
#pragma unroll
    for (int i = 0; i < 8; i++) {
        int gr = rowBase + ty * 8 + i;
        if (gr < M) {
            __half2 h0 = __floats2half2_rn(acc[i][0], acc[i][1]);
            __half2 h1v = __floats2half2_rn(acc[i][2], acc[i][3]);
            __half2 h2v = __floats2half2_rn(acc[i][4], acc[i][5]);
            __half2 h3 = __floats2half2_rn(acc[i][6], acc[i][7]);
            uint4 pk;
            pk.x = *(unsigned*)&h0; pk.y = *(unsigned*)&h1v;
            pk.z = *(unsigned*)&h2v; pk.w = *(unsigned*)&h3;
            *(uint4*)&g_h1h[(size_t)gr * F1 + tx * 8] = pk;
        }
        float ps = 0.f, pd = 0.f;
#pragma unroll
        for (int j = 0; j < 8; j++) {
            ps += acc[i][j] * s_as[cbase + j];
            pd += acc[i][j] * s_ad[cbase + j];
        }
        ps += __shfl_xor_sync(0xffffffffu, ps, 1);
        pd += __shfl_xor_sync(0xffffffffu, pd, 1);
        if ((tx & 1) == 0 && gr < M) {
            g_asrc[gr * H1 + head] = ps;
            g_adst[gr * H1 + head] = pd;
        }
    }
}

// ------------------------- fused layer-1 softmax + aggregation (fp16 gathers) -------------------------
__device__ __forceinline__ void loadH4(int s, int lane, float* f) {
    uint2 u = *(const uint2*)&g_h1h[(size_t)s * F1 + lane * 4];
    float2 p0 = __half22float2(*(__half2*)&u.x);
    float2 p1 = __half22float2(*(__half2*)&u.y);
    f[0] = p0.x; f[1] = p0.y; f[2] = p1.x; f[3] = p1.y;
}

__global__ void node1_kernel() {
    int n = (blockIdx.x * blockDim.x + threadIdx.x) >> 5;
    if (n >= N_NODES) return;
    int lane = threadIdx.x & 31;
    int rs = g_start[n], re = g_start[n + 1];

    float4 ad0 = *(const float4*)&g_adst[n * H1];
    float4 ad1 = *(const float4*)&g_adst[n * H1 + 4];
    float adh[8] = {ad0.x, ad0.y, ad0.z, ad0.w, ad1.x, ad1.y, ad1.z, ad1.w};

    float m[8];
#pragma unroll
    for (int h = 0; h < 8; h++) m[h] = NEG_INF;
    for (int j = rs + lane; j < re; j += 32) {
        int s = g_csr_src[j];
        float4 a0 = *(const float4*)&g_asrc[s * H1];
        float4 a1 = *(const float4*)&g_asrc[s * H1 + 4];
        float ev[8] = {a0.x + adh[0], a0.y + adh[1], a0.z + adh[2], a0.w + adh[3],
                       a1.x + adh[4], a1.y + adh[5], a1.z + adh[6], a1.w + adh[7]};
#pragma unroll
        for (int h = 0; h < 8; h++) m[h] = fmaxf(m[h], leaky(ev[h]));
    }
#pragma unroll
    for (int o = 16; o > 0; o >>= 1)
#pragma unroll
        for (int h = 0; h < 8; h++) m[h] = fmaxf(m[h], __shfl_xor_sync(0xffffffffu, m[h], o));

    int myh = lane >> 2;
    float mh = m[myh];
    float adm = adh[myh];
    float ssum = 0.f;
    float acc0 = 0.f, acc1 = 0.f, acc2 = 0.f, acc3 = 0.f;

    int j = rs;
    for (; j + 3 < re; j += 4) {
        int s0 = g_csr_src[j];
        int s1 = g_csr_src[j + 1];
        int s2 = g_csr_src[j + 2];
        int s3 = g_csr_src[j + 3];
        float av0 = __ldg(&g_asrc[s0 * H1 + myh]);
        float av1 = __ldg(&g_asrc[s1 * H1 + myh]);
        float av2 = __ldg(&g_asrc[s2 * H1 + myh]);
        float av3 = __ldg(&g_asrc[s3 * H1 + myh]);
        float f0[4], f1[4], f2[4], f3[4];
        loadH4(s0, lane, f0);
        loadH4(s1, lane, f1);
        loadH4(s2, lane, f2);
        loadH4(s3, lane, f3);
        float ee0 = __expf(leaky(av0 + adm) - mh);
        float ee1 = __expf(leaky(av1 + adm) - mh);
        float ee2 = __expf(leaky(av2 + adm) - mh);
        float ee3 = __expf(leaky(av3 + adm) - mh);
        ssum += (ee0 + ee1) + (ee2 + ee3);
        acc0 += ee0 * f0[0] + ee1 * f1[0] + ee2 * f2[0] + ee3 * f3[0];
        acc1 += ee0 * f0[1] + ee1 * f1[1] + ee2 * f2[1] + ee3 * f3[1];
        acc2 += ee0 * f0[2] + ee1 * f1[2] + ee2 * f2[2] + ee3 * f3[2];
        acc3 += ee0 * f0[3] + ee1 * f1[3] + ee2 * f2[3] + ee3 * f3[3];
    }
    for (; j < re; j++) {
        int s0 = g_csr_src[j];
        float av0 = __ldg(&g_asrc[s0 * H1 + myh]);
        float f0[4];
        loadH4(s0, lane, f0);
        float ee0 = __expf(leaky(av0 + adm) - mh);
        ssum += ee0;
        acc0 += ee0 * f0[0]; acc1 += ee0 * f0[1]; acc2 += ee0 * f0[2]; acc3 += ee0 * f0[3];
    }
    float inv = 1.f / ssum;
    *(float4*)&g_agg1[(size_t)n * F1 + lane * 4] =
        make_float4(acc0 * inv, acc1 * inv, acc2 * inv, acc3 * inv);
}

// ------------------------- layer 2 projection -------------------------
__global__ void h2_kernel(const float* __restrict__ b1, const float* __restrict__ W2,
                          const float* __restrict__ as2, const float* __restrict__ ad2) {
    int n = (blockIdx.x * blockDim.x + threadIdx.x) >> 5;
    if (n >= N_NODES) return;
    int lane = threadIdx.x & 31;
    float4 hv = *(const float4*)&g_agg1[(size_t)n * F1 + lane * 4];
    float4 bv = *(const float4*)&b1[lane * 4];
    float v0 = hv.x + bv.x, v1 = hv.y + bv.y, v2 = hv.z + bv.z, v3 = hv.w + bv.w;
    v0 = v0 > 0.f ? v0 : expm1f(v0);
    v1 = v1 > 0.f ? v1 : expm1f(v1);
    v2 = v2 > 0.f ? v2 : expm1f(v2);
    v3 = v3 > 0.f ? v3 : expm1f(v3);
    const float4* W4 = (const float4*)W2;
    float4 wa = W4[lane * 2];
    float4 wb = W4[lane * 2 + 1];
    float p0 = v0 * wa.x + v1 * wa.z + v2 * wb.x + v3 * wb.z;
    float p1 = v0 * wa.y + v1 * wa.w + v2 * wb.y + v3 * wb.w;
#pragma unroll
    for (int o = 16; o > 0; o >>= 1) {
        p0 += __shfl_xor_sync(0xffffffffu, p0, o);
        p1 += __shfl_xor_sync(0xffffffffu, p1, o);
    }
    if (lane == 0) {
        g_h2[n * 2] = p0;
        g_h2[n * 2 + 1] = p1;
        g_a2s[n] = p0 * as2[0] + p1 * as2[1];
        g_a2d[n] = p0 * ad2[0] + p1 * ad2[1];
    }
}

// ------------------------- fused layer-2 softmax-aggregate -------------------------
__global__ void node2_kernel(float* __restrict__ out, const float* __restrict__ b2) {
    int n = (blockIdx.x * blockDim.x + threadIdx.x) >> 5;
    if (n >= N_NODES) return;
    int lane = threadIdx.x & 31;
    int rs = g_start[n], re = g_start[n + 1];
    float a2dn = g_a2d[n];

    float m = NEG_INF;
    for (int j = rs + lane; j < re; j += 32)
        m = fmaxf(m, leaky(g_a2s[g_csr_src[j]] + a2dn));
#pragma unroll
    for (int o = 16; o > 0; o >>= 1) m = fmaxf(m, __shfl_xor_sync(0xffffffffu, m, o));

    float S = 0.f, n0 = 0.f, n1 = 0.f;
    for (int j = rs + lane; j < re; j += 32) {
        int s = g_csr_src[j];
        float ee = __expf(leaky(g_a2s[s] + a2dn) - m);
        float2 h = *(const float2*)&g_h2[s * 2];
        S += ee; n0 += ee * h.x; n1 += ee * h.y;
    }
#pragma unroll
    for (int o = 16; o > 0; o >>= 1) {
        S  += __shfl_xor_sync(0xffffffffu, S, o);
        n0 += __shfl_xor_sync(0xffffffffu, n0, o);
        n1 += __shfl_xor_sync(0xffffffffu, n1, o);
    }
    if (lane == 0) {
        float inv = 1.f / S;
        out[n * 2]     = n0 * inv + b2[0];
        out[n * 2 + 1] = n1 * inv + b2[1];
    }
}

// ------------------------- launch -------------------------
extern "C" void kernel_launch(void* const* d_in, const int* in_sizes, int n_in,
                              void* d_out, int out_size) {
    const float* x   = (const float*)d_in[0];
    const void*  ei  = d_in[1];
    const float* W1  = (const float*)d_in[2];
    const float* as1 = (const float*)d_in[3];
    const float* ad1 = (const float*)d_in[4];
    const float* b1  = (const float*)d_in[5];
    const float* W2  = (const float*)d_in[6];
    const float* as2 = (const float*)d_in[7];
    const float* ad2 = (const float*)d_in[8];
    const float* b2  = (const float*)d_in[9];
    float* out = (float*)d_out;

    int E  = in_sizes[1] / 2;
    int ET = E + N_NODES;

    probe_kernel<<<1, 256>>>(ei);
    zero_kernel<<<(N_NODES + 255) / 256, 256>>>();
    convert_kernel<<<(ET + 255) / 256, 256>>>(ei, E, ET);
    scanA_kernel<<<SCAN_NB, 1024>>>();
    scanB_kernel<<<1, 32>>>();
    scanC_kernel<<<(N_NODES + 255) / 256, 256>>>();
    scatter_kernel<<<(ET + 255) / 256, 256>>>(ET);

    gemm1_kernel<<<(N_NODES + BM - 1) / BM, 256>>>(x, W1, as1, ad1, N_NODES);

    int nodeBlocks = (N_NODES * 32 + 255) / 256;
    node1_kernel<<<nodeBlocks, 256>>>();
    h2_kernel<<<nodeBlocks, 256>>>(b1, W2, as2, ad2);
    node2_kernel<<<nodeBlocks, 256>>>(out, b2);
}

// round 6
// speedup vs baseline: 1.3653x; 1.2205x over previous
#include <cuda_runtime.h>
#include <cuda_fp16.h>
#include <math.h>

#define N_NODES 50000
#define FIN 128
#define H1 8
#define F1 128
#define E_MAX 800000
#define ET_MAX (E_MAX + N_NODES)
#define NEG_SLOPE 0.2f
#define SCAN_NB ((N_NODES + 1023) / 1024)   // 49

// ------------------------- scratch -------------------------
__device__ __half g_h1h[N_NODES * F1];     // fp16 x @ W1 (node1 gathers)
__device__ float g_asrc[N_NODES * H1];
__device__ float g_adst[N_NODES * H1];
__device__ float g_h2[N_NODES * 2];
__device__ float g_a2s[N_NODES];
__device__ float g_a2d[N_NODES];
__device__ int   g_src[ET_MAX];
__device__ int   g_dst[ET_MAX];
__device__ int   g_csr_src[ET_MAX];
__device__ int   g_start[N_NODES + 1];
__device__ int   g_deg[N_NODES];
__device__ int   g_cnt[N_NODES];
__device__ int   g_bsum[SCAN_NB];
__device__ int   g_boff[SCAN_NB];
__device__ int   g_is64;

__device__ __forceinline__ float leaky(float v) { return v > 0.f ? v : NEG_SLOPE * v; }

// ------------------------- dtype probe -------------------------
__global__ void probe_kernel(const void* ei) {
    const long long* p = (const long long*)ei;
    int bad = 0;
    for (int i = threadIdx.x; i < 2048; i += 256) {
        long long v = p[i];
        if (v < 0 || v >= (long long)N_NODES) bad = 1;
    }
    bad = __syncthreads_or(bad);
    if (threadIdx.x == 0) g_is64 = bad ? 0 : 1;
}

__global__ void zero_kernel() {
    int i = blockIdx.x * blockDim.x + threadIdx.x;
    if (i < N_NODES) { g_deg[i] = 0; g_cnt[i] = 0; }
}

__global__ void convert_kernel(const void* ei, int E, int ET) {
    int i = blockIdx.x * blockDim.x + threadIdx.x;
    if (i >= ET) return;
    int s, d;
    if (i < E) {
        if (g_is64) {
            const long long* p = (const long long*)ei;
            s = (int)p[i]; d = (int)p[E + i];
        } else {
            const int* p = (const int*)ei;
            s = p[i]; d = p[E + i];
        }
    } else {
        s = d = i - E;
    }
    g_src[i] = s;
    g_dst[i] = d;
    atomicAdd(&g_deg[d], 1);
}

// ------------------------- multi-block scan -------------------------
__global__ void scanA_kernel() {
    int i = blockIdx.x * 1024 + threadIdx.x;
    int v = (i < N_NODES) ? g_deg[i] : 0;
    int lane = threadIdx.x & 31, wid = threadIdx.x >> 5;
    int x = v;
#pragma unroll
    for (int o = 1; o < 32; o <<= 1) {
        int t = __shfl_up_sync(0xffffffffu, x, o);
        if (lane >= o) x += t;
    }
    __shared__ int wsum[32];
    if (lane == 31) wsum[wid] = x;
    __syncthreads();
    if (wid == 0) {
        int y = wsum[lane];
#pragma unroll
        for (int o = 1; o < 32; o <<= 1) {
            int t = __shfl_up_sync(0xffffffffu, y, o);
            if (lane >= o) y += t;
        }
        wsum[lane] = y;
    }
    __syncthreads();
    int incl = x + (wid > 0 ? wsum[wid - 1] : 0);
    if (i < N_NODES) g_start[i] = incl - v;
    if (threadIdx.x == 1023) g_bsum[blockIdx.x] = incl;
}

__global__ void scanB_kernel() {
    int lane = threadIdx.x;
    int i0 = 2 * lane, i1 = 2 * lane + 1;
    int a = (i0 < SCAN_NB) ? g_bsum[i0] : 0;
    int b = (i1 < SCAN_NB) ? g_bsum[i1] : 0;
    int loc = a + b;
    int x = loc;
#pragma unroll
    for (int o = 1; o < 32; o <<= 1) {
        int t = __shfl_up_sync(0xffffffffu, x, o);
        if (lane >= o) x += t;
    }
    int excl = x - loc;
    if (i0 < SCAN_NB) g_boff[i0] = excl;
    if (i1 < SCAN_NB) g_boff[i1] = excl + a;
    if (lane == 31) g_start[N_NODES] = x;
}

__global__ void scanC_kernel() {
    int i = blockIdx.x * blockDim.x + threadIdx.x;
    if (i < N_NODES) g_start[i] += g_boff[i >> 10];
}

__global__ void scatter_kernel(int ET) {
    int i = blockIdx.x * blockDim.x + threadIdx.x;
    if (i >= ET) return;
    int d = g_dst[i];
    int pos = g_start[d] + atomicAdd(&g_cnt[d], 1);
    g_csr_src[pos] = g_src[i];
}

// ------------------------- GEMM: h1 = x @ W1 (fused attdot + fp16 store) -------------------------
#define BM 128
#define BK 8
__global__ void __launch_bounds__(256, 2)
gemm1_kernel(const float* __restrict__ X, const float* __restrict__ W,
             const float* __restrict__ att_s, const float* __restrict__ att_d, int M) {
    __shared__ __align__(16) float As[BK][BM];
    __shared__ __align__(16) float Bs[BK][F1];
    __shared__ float s_as[F1], s_ad[F1];
    int tid = threadIdx.x;
    int tx = tid & 15;
    int ty = tid >> 4;
    int rowBase = blockIdx.x * BM;

    if (tid < F1) { s_as[tid] = att_s[tid]; s_ad[tid] = att_d[tid]; }

    int lrow = tid >> 1;
    int lhalf = tid & 1;
    int grow = rowBase + lrow;
    const float* Xrow = X + (size_t)grow * FIN;
    int wrow = tid >> 5;
    int wcol = (tid & 31) * 4;

    float acc[8][8];
#pragma unroll
    for (int i = 0; i < 8; i++)
#pragma unroll
        for (int j = 0; j < 8; j++) acc[i][j] = 0.f;

    for (int k0 = 0; k0 < FIN; k0 += BK) {
        float4 xv = make_float4(0.f, 0.f, 0.f, 0.f);
        if (grow < M) xv = *(const float4*)(Xrow + k0 + lhalf * 4);
        As[lhalf * 4 + 0][lrow] = xv.x;
        As[lhalf * 4 + 1][lrow] = xv.y;
        As[lhalf * 4 + 2][lrow] = xv.z;
        As[lhalf * 4 + 3][lrow] = xv.w;
        *(float4*)&Bs[wrow][wcol] = *(const float4*)&W[(size_t)(k0 + wrow) * F1 + wcol];
        __syncthreads();
#pragma unroll
        for (int kk = 0; kk < BK; kk++) {
            float4 a0 = *(const float4*)&As[kk][ty * 8];
            float4 a1 = *(const float4*)&As[kk][ty * 8 + 4];
            float4 b0 = *(const float4*)&Bs[kk][tx * 8];
            float4 b1 = *(const float4*)&Bs[kk][tx * 8 + 4];
            float av[8] = {a0.x, a0.y, a0.z, a0.w, a1.x, a1.y, a1.z, a1.w};
            float bv[8] = {b0.x, b0.y, b0.z, b0.w, b1.x, b1.y, b1.z, b1.w};
#pragma unroll
            for (int i = 0; i < 8; i++)
#pragma unroll
                for (int j = 0; j < 8; j++) acc[i][j] += av[i] * bv[j];
        }
        __syncthreads();
    }

    int head = tx >> 1;
    int cbase = head * 16 + (tx & 1) * 8;
#pragma unroll
    for (int i = 0; i < 8; i++) {
        int gr = rowBase + ty * 8 + i;
        if (gr < M) {
            __half2 h0 = __floats2half2_rn(acc[i][0], acc[i][1]);
            __half2 h1v = __floats2half2_rn(acc[i][2], acc[i][3]);
            __half2 h2v = __floats2half2_rn(acc[i][4], acc[i][5]);
            __half2 h3 = __floats2half2_rn(acc[i][6], acc[i][7]);
            uint4 pk;
            pk.x = *(unsigned*)&h0; pk.y = *(unsigned*)&h1v;
            pk.z = *(unsigned*)&h2v; pk.w = *(unsigned*)&h3;
            *(uint4*)&g_h1h[(size_t)gr * F1 + tx * 8] = pk;
        }
        float ps = 0.f, pd = 0.f;
#pragma unroll
        for (int j = 0; j < 8; j++) {
            ps += acc[i][j] * s_as[cbase + j];
            pd += acc[i][j] * s_ad[cbase + j];
        }
        ps += __shfl_xor_sync(0xffffffffu, ps, 1);
        pd += __shfl_xor_sync(0xffffffffu, pd, 1);
        if ((tx & 1) == 0 && gr < M) {
            g_asrc[gr * H1 + head] = ps;
            g_adst[gr * H1 + head] = pd;
        }
    }
}

// ------------------------- fused layer-1: single-pass softmax-aggregate + elu + W2 + att2 dots -------------------------
__device__ __forceinline__ void loadH4(int s, int lane, float* f) {
    uint2 u = *(const uint2*)&g_h1h[(size_t)s * F1 + lane * 4];
    float2 p0 = __half22float2(*(__half2*)&u.x);
    float2 p1 = __half22float2(*(__half2*)&u.y);
    f[0] = p0.x; f[1] = p0.y; f[2] = p1.x; f[3] = p1.y;
}

__global__ void node1_kernel(const float* __restrict__ b1, const float* __restrict__ W2,
                             const float* __restrict__ as2, const float* __restrict__ ad2) {
    int n = (blockIdx.x * blockDim.x + threadIdx.x) >> 5;
    if (n >= N_NODES) return;
    int lane = threadIdx.x & 31;
    int rs = g_start[n], re = g_start[n + 1];

    int myh = lane >> 2;
    float adm = g_adst[n * H1 + myh];
    float ssum = 0.f;
    float acc0 = 0.f, acc1 = 0.f, acc2 = 0.f, acc3 = 0.f;

    int j = rs;
    for (; j + 3 < re; j += 4) {
        int s0 = g_csr_src[j];
        int s1 = g_csr_src[j + 1];
        int s2 = g_csr_src[j + 2];
        int s3 = g_csr_src[j + 3];
        float av0 = __ldg(&g_asrc[s0 * H1 + myh]);
        float av1 = __ldg(&g_asrc[s1 * H1 + myh]);
        float av2 = __ldg(&g_asrc[s2 * H1 + myh]);
        float av3 = __ldg(&g_asrc[s3 * H1 + myh]);
        float f0[4], f1[4], f2[4], f3[4];
        loadH4(s0, lane, f0);
        loadH4(s1, lane, f1);
        loadH4(s2, lane, f2);
        loadH4(s3, lane, f3);
        float ee0 = __expf(leaky(av0 + adm));
        float ee1 = __expf(leaky(av1 + adm));
        float ee2 = __expf(leaky(av2 + adm));
        float ee3 = __expf(leaky(av3 + adm));
        ssum += (ee0 + ee1) + (ee2 + ee3);
        acc0 += ee0 * f0[0] + ee1 * f1[0] + ee2 * f2[0] + ee3 * f3[0];
        acc1 += ee0 * f0[1] + ee1 * f1[1] + ee2 * f2[1] + ee3 * f3[1];
        acc2 += ee0 * f0[2] + ee1 * f1[2] + ee2 * f2[2] + ee3 * f3[2];
        acc3 += ee0 * f0[3] + ee1 * f1[3] + ee2 * f2[3] + ee3 * f3[3];
    }
    for (; j < re; j++) {
        int s0 = g_csr_src[j];
        float av0 = __ldg(&g_asrc[s0 * H1 + myh]);
        float f0[4];
        loadH4(s0, lane, f0);
        float ee0 = __expf(leaky(av0 + adm));
        ssum += ee0;
        acc0 += ee0 * f0[0]; acc1 += ee0 * f0[1]; acc2 += ee0 * f0[2]; acc3 += ee0 * f0[3];
    }
    float inv = 1.f / ssum;

    // fused epilogue: v = elu(agg + b1), then [p0,p1] = v @ W2, att2 dots
    float4 bv = *(const float4*)&b1[lane * 4];
    float v0 = acc0 * inv + bv.x;
    float v1 = acc1 * inv + bv.y;
    float v2 = acc2 * inv + bv.z;
    float v3 = acc3 * inv + bv.w;
    v0 = v0 > 0.f ? v0 : expm1f(v0);
    v1 = v1 > 0.f ? v1 : expm1f(v1);
    v2 = v2 > 0.f ? v2 : expm1f(v2);
    v3 = v3 > 0.f ? v3 : expm1f(v3);
    const float4* W4 = (const float4*)W2;
    float4 wa = W4[lane * 2];
    float4 wb = W4[lane * 2 + 1];
    float p0 = v0 * wa.x + v1 * wa.z + v2 * wb.x + v3 * wb.z;
    float p1 = v0 * wa.y + v1 * wa.w + v2 * wb.y + v3 * wb.w;
#pragma unroll
    for (int o = 16; o > 0; o >>= 1) {
        p0 += __shfl_xor_sync(0xffffffffu, p0, o);
        p1 += __shfl_xor_sync(0xffffffffu, p1, o);
    }
    if (lane == 0) {
        g_h2[n * 2]     = p0;
        g_h2[n * 2 + 1] = p1;
        g_a2s[n] = p0 * as2[0] + p1 * as2[1];
        g_a2d[n] = p0 * ad2[0] + p1 * ad2[1];
    }
}

// ------------------------- fused layer-2: single-pass softmax-aggregate -------------------------
__global__ void node2_kernel(float* __restrict__ out, const float* __restrict__ b2) {
    int n = (blockIdx.x * blockDim.x + threadIdx.x) >> 5;
    if (n >= N_NODES) return;
    int lane = threadIdx.x & 31;
    int rs = g_start[n], re = g_start[n + 1];
    float a2dn = g_a2d[n];

    float S = 0.f, n0 = 0.f, n1 = 0.f;
    for (int j = rs + lane; j < re; j += 32) {
        int s = g_csr_src[j];
        float ee = __expf(leaky(g_a2s[s] + a2dn));
        float2 h = *(const float2*)&g_h2[s * 2];
        S += ee; n0 += ee * h.x; n1 += ee * h.y;
    }
#pragma unroll
    for (int o = 16; o > 0; o >>= 1) {
        S  += __shfl_xor_sync(0xffffffffu, S, o);
        n0 += __shfl_xor_sync(0xffffffffu, n0, o);
        n1 += __shfl_xor_sync(0xffffffffu, n1, o);
    }
    if (lane == 0) {
        float inv = 1.f / S;
        out[n * 2]     = n0 * inv + b2[0];
        out[n * 2 + 1] = n1 * inv + b2[1];
    }
}

// ------------------------- launch -------------------------
extern "C" void kernel_launch(void* const* d_in, const int* in_sizes, int n_in,
                              void* d_out, int out_size) {
    const float* x   = (const float*)d_in[0];
    const void*  ei  = d_in[1];
    const float* W1  = (const float*)d_in[2];
    const float* as1 = (const float*)d_in[3];
    const float* ad1 = (const float*)d_in[4];
    const float* b1  = (const float*)d_in[5];
    const float* W2  = (const float*)d_in[6];
    const float* as2 = (const float*)d_in[7];
    const float* ad2 = (const float*)d_in[8];
    const float* b2  = (const float*)d_in[9];
    float* out = (float*)d_out;

    int E  = in_sizes[1] / 2;
    int ET = E + N_NODES;

    probe_kernel<<<1, 256>>>(ei);
    zero_kernel<<<(N_NODES + 255) / 256, 256>>>();
    convert_kernel<<<(ET + 255) / 256, 256>>>(ei, E, ET);
    scanA_kernel<<<SCAN_NB, 1024>>>();
    scanB_kernel<<<1, 32>>>();
    scanC_kernel<<<(N_NODES + 255) / 256, 256>>>();
    scatter_kernel<<<(ET + 255) / 256, 256>>>(ET);

    gemm1_kernel<<<(N_NODES + BM - 1) / BM, 256>>>(x, W1, as1, ad1, N_NODES);

    int nodeBlocks = (N_NODES * 32 + 255) / 256;
    node1_kernel<<<nodeBlocks, 256>>>(b1, W2, as2, ad2);
    node2_kernel<<<nodeBlocks, 256>>>(out, b2);
}